// round 10
// baseline (speedup 1.0000x reference)
#include <cuda_runtime.h>
#include <cuda_fp16.h>
#include <cstdint>

#define BB 4
#define NN 4096
#define EE 2048
#define CC 64
#define ECAP 352   // deg_e mean 205, sd~14
#define NCAP 224   // deg_n mean 102, sd~10
#define EBW 128    // words per edge bitmap (4096 node bits)
#define NBW 64     // words per node bitmap (2048 edge bits)

typedef unsigned long long ull;
typedef unsigned short u16;

// ---- scratch (no cudaMalloc allowed) ----
__device__ __half   g_xt[BB * NN * CC];               // 2 MB (fp16)
__device__ __half   g_he[BB * EE * CC];               // 1 MB (fp16)
__device__ unsigned g_ebm[(size_t)BB * EE * EBW];     // 4 MB edge bitmaps (natural)
__device__ unsigned g_nbm[(size_t)BB * NN * NBW];     // 4 MB node bitmaps (natural)

__device__ __forceinline__ ull fadd2(ull a, ull b) {
    ull d;
    asm("add.rn.f32x2 %0, %1, %2;" : "=l"(d) : "l"(a), "l"(b));
    return d;
}
__device__ __forceinline__ ull f2ull(float2 f) { return *reinterpret_cast<ull*>(&f); }

// ---------------- K1: xt = x @ theta (warp per row, fp16 out) ----------------
__global__ __launch_bounds__(256)
void xt_kernel(const float* __restrict__ x, const float* __restrict__ theta) {
    __shared__ float th[CC * 66];
    const int tid = threadIdx.x;
    for (int i = tid; i < CC * CC; i += 256) {
        int k = i >> 6, c = i & 63;
        th[k * 66 + c] = theta[i];
    }
    __syncthreads();

    const int lane = tid & 31;
    const int row = blockIdx.x * 8 + (tid >> 5);
    const float2 xv = ((const float2*)(x + (size_t)row * CC))[lane];
    float a0 = 0.f, a1 = 0.f;
#pragma unroll
    for (int k = 0; k < CC; k++) {
        const float xs = (k & 1) ? __shfl_sync(0xffffffffu, xv.y, k >> 1)
                                 : __shfl_sync(0xffffffffu, xv.x, k >> 1);
        const float2 t = *(const float2*)&th[k * 66 + lane * 2];
        a0 = fmaf(xs, t.x, a0);
        a1 = fmaf(xs, t.y, a1);
    }
    ((__half2*)(g_xt + (size_t)row * CC))[lane] = __float22half2_rn(make_float2(a0, a1));
}

// ---------------- K2: build — atomic-free tile-transpose -> both bitmaps ----------
// CTA owns a 32-node x 128-edge tile of H. smem layout XOR-swizzled on the low 5
// column bits so BOTH row-reads and column-reads are bank-conflict-free.
// Each bitmap word is produced by exactly one warp ballot and stored once (STG).
__global__ __launch_bounds__(256)
void build_kernel(const float* __restrict__ H) {
    __shared__ float tile[32 * 128];    // 16 KB
    const int tid = threadIdx.x;
    const int lane = tid & 31;
    const int wid = tid >> 5;
    const int eblk = blockIdx.x;        // 0..15   (128 edges each)
    const int nblk = blockIdx.y;        // 0..127  (32 nodes each)
    const int b = blockIdx.z;

    const float* __restrict__ Hp =
        H + ((size_t)(b * NN + nblk * 32)) * EE + eblk * 128;

    // load: warp w covers rows w, w+8, w+16, w+24 (512B coalesced per row)
#pragma unroll
    for (int p = 0; p < 4; p++) {
        const int r = wid + p * 8;
        const float4 v = ((const float4*)(Hp + (size_t)r * EE))[lane];
        const int cb = lane * 4;        // logical col of v.x
        float* tr = &tile[r * 128];
        tr[(cb & ~31) | ((cb ^ r) & 31)]             = v.x;
        tr[((cb + 1) & ~31) | (((cb + 1) ^ r) & 31)] = v.y;
        tr[((cb + 2) & ~31) | (((cb + 2) ^ r) & 31)] = v.z;
        tr[((cb + 3) & ~31) | (((cb + 3) ^ r) & 31)] = v.w;
    }
    __syncthreads();

    // pass 1: node bitmaps (natural: bit l of word wd <-> e = eblk*128 + wd*32 + l)
#pragma unroll
    for (int p = 0; p < 4; p++) {
        const int r = wid + p * 8;
        unsigned w0, w1, w2, w3;
        {
            const float v = tile[r * 128 + 0 * 32 + ((lane ^ r) & 31)];
            w0 = __ballot_sync(0xffffffffu, v != 0.f);
        }
        {
            const float v = tile[r * 128 + 1 * 32 + ((lane ^ r) & 31)];
            w1 = __ballot_sync(0xffffffffu, v != 0.f);
        }
        {
            const float v = tile[r * 128 + 2 * 32 + ((lane ^ r) & 31)];
            w2 = __ballot_sync(0xffffffffu, v != 0.f);
        }
        {
            const float v = tile[r * 128 + 3 * 32 + ((lane ^ r) & 31)];
            w3 = __ballot_sync(0xffffffffu, v != 0.f);
        }
        if (lane == 0)
            *(uint4*)&g_nbm[(size_t)(b * NN + nblk * 32 + r) * NBW + eblk * 4] =
                make_uint4(w0, w1, w2, w3);
    }

    // pass 2: edge bitmaps (bit l of word nblk <-> node nblk*32 + l)
#pragma unroll
    for (int q = 0; q < 16; q++) {
        const int e = wid * 16 + q;     // logical col 0..127
        const float v = tile[lane * 128 + (e & ~31) + ((e ^ lane) & 31)];
        const unsigned bw = __ballot_sync(0xffffffffu, v != 0.f);
        if (lane == 0)
            g_ebm[(size_t)(b * EE + eblk * 128 + e) * EBW + nblk] = bw;
    }
}

// ---------------- K3/K4: aggregation, fp16 rows, depth-2 fp16 pair tree -----------
// Warp per output row; decode natural bitmap -> smem u16 list; half-warp per
// gathered row (16 lanes x uint2); 4 rows combined in fp16 (3 HADD2) then one
// convert + packed fp32 accumulate.
template <int WPL, int CAP, bool HASBIAS, int M, int SRCROWS, bool OUTHALF>
__global__ __launch_bounds__(256)
void agg_kernel(const unsigned* __restrict__ bm, const __half* __restrict__ src,
                void* __restrict__ dstv, const float* __restrict__ bias) {
    __shared__ u16 sidx[8][CAP];

    const int tid = threadIdx.x;
    const int lane = tid & 31;
    const int wid = tid >> 5;
    const int gw = blockIdx.x * 8 + wid;   // (b,m)
    const int b = gw / M;

    // ---- decode bitmap -> smem index list ----
    unsigned w[WPL];
    const unsigned* __restrict__ W = bm + (size_t)gw * (WPL * 32);
    if (WPL == 4) {
        const uint4 v = ((const uint4*)W)[lane];
        w[0] = v.x; w[1] = v.y; w[2] = v.z; w[3] = v.w;
    } else {
        const uint2 v = ((const uint2*)W)[lane];
        w[0] = v.x; w[1] = v.y;
    }
    int cnt = 0;
#pragma unroll
    for (int k = 0; k < WPL; k++) cnt += __popc(w[k]);

    int pre = cnt;
#pragma unroll
    for (int d = 1; d < 32; d <<= 1) {
        int v = __shfl_up_sync(0xffffffffu, pre, d);
        if (lane >= d) pre += v;
    }
    const int deg = __shfl_sync(0xffffffffu, pre, 31);
    int off = pre - cnt;

    u16* __restrict__ s = sidx[wid];
#pragma unroll
    for (int k = 0; k < WPL; k++) {
        const int wi = lane * WPL + k;
        unsigned bits = w[k];
        while (bits) {
            const int t = __ffs(bits) - 1;
            bits &= bits - 1;
            if (off < CAP) s[off] = (u16)(wi * 32 + t);
            off++;
        }
    }
    __syncwarp();

    // ---- gather: half-warp per row; 8 rows/iter; depth-2 fp16 tree ----
    const int half = lane >> 4;
    const int hl = lane & 15;             // uint2 = cols hl*4 .. hl*4+3
    const uint2* __restrict__ S = (const uint2*)src + (size_t)b * (SRCROWS * 16);

    ull accA = 0ull, accB = 0ull;
    int i = 0;
    for (; i + 8 <= deg; i += 8) {
        const int r0 = (int)s[i + half];
        const int r1 = (int)s[i + 2 + half];
        const int r2 = (int)s[i + 4 + half];
        const int r3 = (int)s[i + 6 + half];
        const uint2 u0 = S[r0 * 16 + hl];
        const uint2 u1 = S[r1 * 16 + hl];
        const uint2 u2 = S[r2 * 16 + hl];
        const uint2 u3 = S[r3 * 16 + hl];
        const __half2 pa = __hadd2(__hadd2(*(const __half2*)&u0.x, *(const __half2*)&u1.x),
                                   __hadd2(*(const __half2*)&u2.x, *(const __half2*)&u3.x));
        const __half2 pb = __hadd2(__hadd2(*(const __half2*)&u0.y, *(const __half2*)&u1.y),
                                   __hadd2(*(const __half2*)&u2.y, *(const __half2*)&u3.y));
        accA = fadd2(accA, f2ull(__half22float2(pa)));
        accB = fadd2(accB, f2ull(__half22float2(pb)));
    }
    for (; i + 4 <= deg; i += 4) {
        const int r0 = (int)s[i + half];
        const int r1 = (int)s[i + 2 + half];
        const uint2 u0 = S[r0 * 16 + hl];
        const uint2 u1 = S[r1 * 16 + hl];
        const __half2 pa = __hadd2(*(const __half2*)&u0.x, *(const __half2*)&u1.x);
        const __half2 pb = __hadd2(*(const __half2*)&u0.y, *(const __half2*)&u1.y);
        accA = fadd2(accA, f2ull(__half22float2(pa)));
        accB = fadd2(accB, f2ull(__half22float2(pb)));
    }
    if (i + 2 <= deg) {
        const int r = (int)s[i + half];
        const uint2 u = S[r * 16 + hl];
        accA = fadd2(accA, f2ull(__half22float2(*(const __half2*)&u.x)));
        accB = fadd2(accB, f2ull(__half22float2(*(const __half2*)&u.y)));
        i += 2;
    }
    if (i < deg && half == 0) {
        const int r = (int)s[i];
        const uint2 u = S[r * 16 + hl];
        accA = fadd2(accA, f2ull(__half22float2(*(const __half2*)&u.x)));
        accB = fadd2(accB, f2ull(__half22float2(*(const __half2*)&u.y)));
    }

    // combine halves
    float v0 = ((const float2*)&accA)->x;
    float v1 = ((const float2*)&accA)->y;
    float v2 = ((const float2*)&accB)->x;
    float v3 = ((const float2*)&accB)->y;
    v0 += __shfl_xor_sync(0xffffffffu, v0, 16);
    v1 += __shfl_xor_sync(0xffffffffu, v1, 16);
    v2 += __shfl_xor_sync(0xffffffffu, v2, 16);
    v3 += __shfl_xor_sync(0xffffffffu, v3, 16);

    const float inv = 1.0f / (float)deg;   // degrees guaranteed > 0
    v0 *= inv; v1 *= inv; v2 *= inv; v3 *= inv;
    if (HASBIAS) {
        const float4 bv = ((const float4*)bias)[hl];
        v0 += bv.x; v1 += bv.y; v2 += bv.z; v3 += bv.w;
    }
    if (half == 0) {
        if (OUTHALF) {
            __half2 h0 = __float22half2_rn(make_float2(v0, v1));
            __half2 h1 = __float22half2_rn(make_float2(v2, v3));
            uint2 o;
            o.x = *(unsigned*)&h0;
            o.y = *(unsigned*)&h1;
            ((uint2*)((__half*)dstv + (size_t)gw * CC))[hl] = o;
        } else {
            ((float4*)((float*)dstv + (size_t)gw * CC))[hl] =
                make_float4(v0, v1, v2, v3);
        }
    }
}

// ---------------- launch ----------------
extern "C" void kernel_launch(void* const* d_in, const int* in_sizes, int n_in,
                              void* d_out, int out_size) {
    const float* x = (const float*)d_in[0];
    const float* H = (const float*)d_in[1];
    const float* theta = (const float*)d_in[2];
    const float* bias = (const float*)d_in[3];
    float* out = (float*)d_out;

    __half *xt, *he;
    unsigned *ebm, *nbm;
    cudaGetSymbolAddress((void**)&xt, g_xt);
    cudaGetSymbolAddress((void**)&he, g_he);
    cudaGetSymbolAddress((void**)&ebm, g_ebm);
    cudaGetSymbolAddress((void**)&nbm, g_nbm);

    // K1: node transform -> fp16 xt
    xt_kernel<<<(BB * NN) / 8, 256>>>(x, theta);
    // K2: tile-transpose build -> both bitmaps, natural layout, no atomics
    build_kernel<<<dim3(EE / 128, NN / 32, BB), 256>>>(H);
    // K3: he = mean_{n in e} xt[n]  (fp16 out)
    agg_kernel<4, ECAP, false, EE, NN, true>
        <<<(BB * EE) / 8, 256>>>(ebm, xt, he, nullptr);
    // K4: out = mean_{e in n} he[e] + bias  (fp32 out)
    agg_kernel<2, NCAP, true, NN, EE, false>
        <<<(BB * NN) / 8, 256>>>(nbm, he, out, bias);
}

// round 13
// speedup vs baseline: 1.0442x; 1.0442x over previous
#include <cuda_runtime.h>
#include <cuda_fp16.h>
#include <cstdint>

#define BB 4
#define NN 4096
#define EE 2048
#define CC 64
#define ECAP 352   // deg_e mean 205, sd~14
#define NCAP 224   // deg_n mean 102, sd~10
#define EBW 128    // words per edge bitmap (4096 node bits)
#define NBW 64     // words per node bitmap (2048 edge bits)

typedef unsigned long long ull;
typedef unsigned short u16;

// ---- scratch (no cudaMalloc allowed) ----
__device__ __half   g_xt[BB * NN * CC];               // 2 MB (fp16)
__device__ __half   g_he[BB * EE * CC];               // 1 MB (fp16)
__device__ unsigned g_ebm[(size_t)BB * EE * EBW];     // 4 MB edge bitmaps (natural)
__device__ unsigned g_nbm[(size_t)BB * NN * NBW];     // 4 MB node bitmaps (natural)

__device__ __forceinline__ ull fadd2(ull a, ull b) {
    ull d;
    asm("add.rn.f32x2 %0, %1, %2;" : "=l"(d) : "l"(a), "l"(b));
    return d;
}
__device__ __forceinline__ ull f2ull(float2 f) { return *reinterpret_cast<ull*>(&f); }

// ---------------- noop: occupies profile slot so build lands at launch idx 3 -------
__global__ void noop_kernel() {}

// ---------------- zero edge bitmaps ----------------
__global__ __launch_bounds__(256) void zero_kernel() {
    const int t = blockIdx.x * 256 + threadIdx.x;   // 262144 * uint4 = 4 MB
    ((uint4*)g_ebm)[t] = make_uint4(0u, 0u, 0u, 0u);
}

// ---------------- xt = x @ theta (warp per row, fp16 out) ----------------
__global__ __launch_bounds__(256)
void xt_kernel(const float* __restrict__ x, const float* __restrict__ theta) {
    __shared__ float th[CC * 66];
    const int tid = threadIdx.x;
    for (int i = tid; i < CC * CC; i += 256) {
        int k = i >> 6, c = i & 63;
        th[k * 66 + c] = theta[i];
    }
    __syncthreads();

    const int lane = tid & 31;
    const int row = blockIdx.x * 8 + (tid >> 5);
    const float2 xv = ((const float2*)(x + (size_t)row * CC))[lane];
    float a0 = 0.f, a1 = 0.f;
#pragma unroll
    for (int k = 0; k < CC; k++) {
        const float xs = (k & 1) ? __shfl_sync(0xffffffffu, xv.y, k >> 1)
                                 : __shfl_sync(0xffffffffu, xv.x, k >> 1);
        const float2 t = *(const float2*)&th[k * 66 + lane * 2];
        a0 = fmaf(xs, t.x, a0);
        a1 = fmaf(xs, t.y, a1);
    }
    ((__half2*)(g_xt + (size_t)row * CC))[lane] = __float22half2_rn(make_float2(a0, a1));
}

// ---------------- build: 2 warps per node row, prefetch 8; both bitmaps natural ----
// ebm: fire-and-forget RED.OR (word n>>5, bit n&31).
// nbm: nibble-pack + 3x shfl_xor OR-reduce; after 8 chunks each lane holds exactly
// one natural word: index = w2*32 + 4*(lane&7) + (lane>>3).
__global__ __launch_bounds__(256)
void build_kernel(const float* __restrict__ H) {
    const int tid = threadIdx.x;
    const int lane = tid & 31;
    const int w2 = (tid >> 5) & 1;                      // row half
    const int gw = blockIdx.x * 4 + (tid >> 6);         // (b,n)
    const int n = gw & (NN - 1);
    const int b = gw >> 12;

    const float4* __restrict__ Hrow = (const float4*)(H + (size_t)gw * EE);
    unsigned* __restrict__ ebm = g_ebm + (size_t)b * EE * EBW + (n >> 5);
    const unsigned bitv = 1u << (n & 31);
    const int cbase = w2 * 8;

    // prefetch whole half-row: 8 independent LDG.128
    float4 hreg[8];
#pragma unroll
    for (int lc = 0; lc < 8; lc++)
        hreg[lc] = Hrow[(cbase + lc) * 32 + lane];

    unsigned myword = 0;
    const int mylc = lane & 7;
#pragma unroll
    for (int lc = 0; lc < 8; lc++) {
        const float4 h = hreg[lc];
        const int e0 = (cbase + lc) * 128 + lane * 4;
        const int c0 = h.x != 0.f, c1 = h.y != 0.f, c2 = h.z != 0.f, c3 = h.w != 0.f;

        if (c0) atomicOr(&ebm[(size_t)(e0 + 0) * EBW], bitv);
        if (c1) atomicOr(&ebm[(size_t)(e0 + 1) * EBW], bitv);
        if (c2) atomicOr(&ebm[(size_t)(e0 + 2) * EBW], bitv);
        if (c3) atomicOr(&ebm[(size_t)(e0 + 3) * EBW], bitv);

        // natural nbm word for this chunk within each group of 8 lanes
        unsigned v = (unsigned)(c0 | (c1 << 1) | (c2 << 2) | (c3 << 3)) << ((lane & 7) * 4);
        v |= __shfl_xor_sync(0xffffffffu, v, 1);
        v |= __shfl_xor_sync(0xffffffffu, v, 2);
        v |= __shfl_xor_sync(0xffffffffu, v, 4);
        if (mylc == lc) myword = v;
    }
    // lane holds natural word idx = w2*32 + 4*mylc + (lane>>3)
    g_nbm[(size_t)gw * NBW + w2 * 32 + 4 * mylc + (lane >> 3)] = myword;
}

// ---------------- agg: fp16 rows, natural bitmap decode, depth-2 fp16 tree ---------
template <int WPL, int CAP, bool HASBIAS, int M, int SRCROWS, bool OUTHALF>
__global__ __launch_bounds__(256)
void agg_kernel(const unsigned* __restrict__ bm, const __half* __restrict__ src,
                void* __restrict__ dstv, const float* __restrict__ bias) {
    __shared__ u16 sidx[8][CAP];

    const int tid = threadIdx.x;
    const int lane = tid & 31;
    const int wid = tid >> 5;
    const int gw = blockIdx.x * 8 + wid;   // (b,m)
    const int b = gw / M;

    // ---- decode bitmap -> smem index list ----
    unsigned w[WPL];
    const unsigned* __restrict__ W = bm + (size_t)gw * (WPL * 32);
    if (WPL == 4) {
        const uint4 v = ((const uint4*)W)[lane];
        w[0] = v.x; w[1] = v.y; w[2] = v.z; w[3] = v.w;
    } else {
        const uint2 v = ((const uint2*)W)[lane];
        w[0] = v.x; w[1] = v.y;
    }
    int cnt = 0;
#pragma unroll
    for (int k = 0; k < WPL; k++) cnt += __popc(w[k]);

    int pre = cnt;
#pragma unroll
    for (int d = 1; d < 32; d <<= 1) {
        int v = __shfl_up_sync(0xffffffffu, pre, d);
        if (lane >= d) pre += v;
    }
    const int deg = __shfl_sync(0xffffffffu, pre, 31);
    int off = pre - cnt;

    u16* __restrict__ s = sidx[wid];
#pragma unroll
    for (int k = 0; k < WPL; k++) {
        const int wi = lane * WPL + k;
        unsigned bits = w[k];
        while (bits) {
            const int t = __ffs(bits) - 1;
            bits &= bits - 1;
            if (off < CAP) s[off] = (u16)(wi * 32 + t);
            off++;
        }
    }
    __syncwarp();

    // ---- gather: half-warp per row; 8 rows/iter; depth-2 fp16 tree ----
    const int half = lane >> 4;
    const int hl = lane & 15;             // uint2 = cols hl*4 .. hl*4+3
    const uint2* __restrict__ S = (const uint2*)src + (size_t)b * (SRCROWS * 16);

    ull accA = 0ull, accB = 0ull;
    int i = 0;
    for (; i + 8 <= deg; i += 8) {
        const int r0 = (int)s[i + half];
        const int r1 = (int)s[i + 2 + half];
        const int r2 = (int)s[i + 4 + half];
        const int r3 = (int)s[i + 6 + half];
        const uint2 u0 = S[r0 * 16 + hl];
        const uint2 u1 = S[r1 * 16 + hl];
        const uint2 u2 = S[r2 * 16 + hl];
        const uint2 u3 = S[r3 * 16 + hl];
        const __half2 pa = __hadd2(__hadd2(*(const __half2*)&u0.x, *(const __half2*)&u1.x),
                                   __hadd2(*(const __half2*)&u2.x, *(const __half2*)&u3.x));
        const __half2 pb = __hadd2(__hadd2(*(const __half2*)&u0.y, *(const __half2*)&u1.y),
                                   __hadd2(*(const __half2*)&u2.y, *(const __half2*)&u3.y));
        accA = fadd2(accA, f2ull(__half22float2(pa)));
        accB = fadd2(accB, f2ull(__half22float2(pb)));
    }
    for (; i + 4 <= deg; i += 4) {
        const int r0 = (int)s[i + half];
        const int r1 = (int)s[i + 2 + half];
        const uint2 u0 = S[r0 * 16 + hl];
        const uint2 u1 = S[r1 * 16 + hl];
        const __half2 pa = __hadd2(*(const __half2*)&u0.x, *(const __half2*)&u1.x);
        const __half2 pb = __hadd2(*(const __half2*)&u0.y, *(const __half2*)&u1.y);
        accA = fadd2(accA, f2ull(__half22float2(pa)));
        accB = fadd2(accB, f2ull(__half22float2(pb)));
    }
    if (i + 2 <= deg) {
        const int r = (int)s[i + half];
        const uint2 u = S[r * 16 + hl];
        accA = fadd2(accA, f2ull(__half22float2(*(const __half2*)&u.x)));
        accB = fadd2(accB, f2ull(__half22float2(*(const __half2*)&u.y)));
        i += 2;
    }
    if (i < deg && half == 0) {
        const int r = (int)s[i];
        const uint2 u = S[r * 16 + hl];
        accA = fadd2(accA, f2ull(__half22float2(*(const __half2*)&u.x)));
        accB = fadd2(accB, f2ull(__half22float2(*(const __half2*)&u.y)));
    }

    // combine halves
    float v0 = ((const float2*)&accA)->x;
    float v1 = ((const float2*)&accA)->y;
    float v2 = ((const float2*)&accB)->x;
    float v3 = ((const float2*)&accB)->y;
    v0 += __shfl_xor_sync(0xffffffffu, v0, 16);
    v1 += __shfl_xor_sync(0xffffffffu, v1, 16);
    v2 += __shfl_xor_sync(0xffffffffu, v2, 16);
    v3 += __shfl_xor_sync(0xffffffffu, v3, 16);

    const float inv = 1.0f / (float)deg;   // degrees guaranteed > 0
    v0 *= inv; v1 *= inv; v2 *= inv; v3 *= inv;
    if (HASBIAS) {
        const float4 bv = ((const float4*)bias)[hl];
        v0 += bv.x; v1 += bv.y; v2 += bv.z; v3 += bv.w;
    }
    if (half == 0) {
        if (OUTHALF) {
            __half2 h0 = __float22half2_rn(make_float2(v0, v1));
            __half2 h1 = __float22half2_rn(make_float2(v2, v3));
            uint2 o;
            o.x = *(unsigned*)&h0;
            o.y = *(unsigned*)&h1;
            ((uint2*)((__half*)dstv + (size_t)gw * CC))[hl] = o;
        } else {
            ((float4*)((float*)dstv + (size_t)gw * CC))[hl] =
                make_float4(v0, v1, v2, v3);
        }
    }
}

// ---------------- launch ----------------
extern "C" void kernel_launch(void* const* d_in, const int* in_sizes, int n_in,
                              void* d_out, int out_size) {
    const float* x = (const float*)d_in[0];
    const float* H = (const float*)d_in[1];
    const float* theta = (const float*)d_in[2];
    const float* bias = (const float*)d_in[3];
    float* out = (float*)d_out;

    __half *xt, *he;
    unsigned *ebm, *nbm;
    cudaGetSymbolAddress((void**)&xt, g_xt);
    cudaGetSymbolAddress((void**)&he, g_he);
    cudaGetSymbolAddress((void**)&ebm, g_ebm);
    cudaGetSymbolAddress((void**)&nbm, g_nbm);

    // order chosen so build_kernel is launch index 3 (the one ncu captures)
    xt_kernel<<<(BB * NN) / 8, 256>>>(x, theta);                 // 0
    zero_kernel<<<1024, 256>>>();                                // 1
    noop_kernel<<<1, 32>>>();                                    // 2
    build_kernel<<<(BB * NN) / 4, 256>>>(H);                     // 3  <- profiled
    agg_kernel<4, ECAP, false, EE, NN, true>                     // 4
        <<<(BB * EE) / 8, 256>>>(ebm, xt, he, nullptr);
    agg_kernel<2, NCAP, true, NN, EE, false>                     // 5
        <<<(BB * NN) / 8, 256>>>(nbm, he, out, bias);
}

// round 14
// speedup vs baseline: 1.2559x; 1.2027x over previous
#include <cuda_runtime.h>
#include <cuda_fp16.h>
#include <cstdint>

#define BB 4
#define NN 4096
#define EE 2048
#define CC 64
#define ECAP 352   // deg_e mean 205, sd~14
#define NCAP 224   // deg_n mean 102, sd~10
#define EBW 128    // words per edge bitmap (4096 node bits)
#define NBW 64     // words per node bitmap (2048 edge bits)

typedef unsigned long long ull;

// ---- scratch (no cudaMalloc allowed) ----
__device__ __half   g_xt[BB * NN * CC];               // 2 MB (fp16)
__device__ __half   g_he[BB * EE * CC];               // 1 MB (fp16)
__device__ unsigned g_ebm[(size_t)BB * EE * EBW];     // 4 MB edge bitmaps (natural)
__device__ unsigned g_nbm[(size_t)BB * NN * NBW];     // 4 MB node bitmaps (natural)

__device__ __forceinline__ ull fadd2(ull a, ull b) {
    ull d;
    asm("add.rn.f32x2 %0, %1, %2;" : "=l"(d) : "l"(a), "l"(b));
    return d;
}
__device__ __forceinline__ ull f2ull(float2 f) { return *reinterpret_cast<ull*>(&f); }

// ---------------- zero edge bitmaps (must precede build's atomics) ----------------
__global__ __launch_bounds__(256) void zero_kernel() {
    const int t = blockIdx.x * 256 + threadIdx.x;   // 262144 * uint4 = 4 MB
    ((uint4*)g_ebm)[t] = make_uint4(0u, 0u, 0u, 0u);
}

// ---------------- fused: xt role (CTAs [0,2048)) + build role ([2048,6144)) --------
// xt: warp per row, fp16 out. build: 2 warps per node row, prefetch 8 via __ldcs;
// ebm by fire-and-forget RED.OR; nbm natural via nibble-pack + 3x shfl_xor.
__global__ __launch_bounds__(256, 5)
void buildxt_kernel(const float* __restrict__ H, const float* __restrict__ x,
                    const float* __restrict__ theta) {
    __shared__ float th[CC * 66];
    const int tid = threadIdx.x;
    const int lane = tid & 31;

    if (blockIdx.x < (BB * NN) / 8) {
        // ---- xt role ----
        for (int i = tid; i < CC * CC; i += 256) {
            int k = i >> 6, c = i & 63;
            th[k * 66 + c] = theta[i];
        }
        __syncthreads();

        const int row = blockIdx.x * 8 + (tid >> 5);
        const float2 xv = ((const float2*)(x + (size_t)row * CC))[lane];
        float a0 = 0.f, a1 = 0.f;
#pragma unroll
        for (int k = 0; k < CC; k++) {
            const float xs = (k & 1) ? __shfl_sync(0xffffffffu, xv.y, k >> 1)
                                     : __shfl_sync(0xffffffffu, xv.x, k >> 1);
            const float2 t = *(const float2*)&th[k * 66 + lane * 2];
            a0 = fmaf(xs, t.x, a0);
            a1 = fmaf(xs, t.y, a1);
        }
        ((__half2*)(g_xt + (size_t)row * CC))[lane] =
            __float22half2_rn(make_float2(a0, a1));
    } else {
        // ---- build role ----
        const int w2 = (tid >> 5) & 1;                          // row half
        const int gw = (blockIdx.x - (BB * NN) / 8) * 4 + (tid >> 6);  // (b,n)
        const int n = gw & (NN - 1);
        const int b = gw >> 12;

        const float4* __restrict__ Hrow = (const float4*)(H + (size_t)gw * EE);
        unsigned* __restrict__ ebm = g_ebm + (size_t)b * EE * EBW + (n >> 5);
        const unsigned bitv = 1u << (n & 31);
        const int cbase = w2 * 8;

        float4 hreg[8];
#pragma unroll
        for (int lc = 0; lc < 8; lc++)
            hreg[lc] = __ldcs(&Hrow[(cbase + lc) * 32 + lane]);

        unsigned myword = 0;
        const int mylc = lane & 7;
#pragma unroll
        for (int lc = 0; lc < 8; lc++) {
            const float4 h = hreg[lc];
            const int e0 = (cbase + lc) * 128 + lane * 4;
            const int c0 = h.x != 0.f, c1 = h.y != 0.f, c2 = h.z != 0.f, c3 = h.w != 0.f;

            if (c0) atomicOr(&ebm[(size_t)(e0 + 0) * EBW], bitv);
            if (c1) atomicOr(&ebm[(size_t)(e0 + 1) * EBW], bitv);
            if (c2) atomicOr(&ebm[(size_t)(e0 + 2) * EBW], bitv);
            if (c3) atomicOr(&ebm[(size_t)(e0 + 3) * EBW], bitv);

            unsigned v = (unsigned)(c0 | (c1 << 1) | (c2 << 2) | (c3 << 3))
                         << ((lane & 7) * 4);
            v |= __shfl_xor_sync(0xffffffffu, v, 1);
            v |= __shfl_xor_sync(0xffffffffu, v, 2);
            v |= __shfl_xor_sync(0xffffffffu, v, 4);
            if (mylc == lc) myword = v;
        }
        g_nbm[(size_t)gw * NBW + w2 * 32 + 4 * mylc + (lane >> 3)] = myword;
    }
}

// ---------------- agg: fp16 rows; byte-offset list, 8-block half-permuted ----------
// Slot layout per full 8-block: {0,2,4,6 | 1,3,5,7} (global offsets), so half h
// reads its 4 row offsets with one aligned LDS.128 at &s[i + h*4]. Accumulation
// pair order identical to prior rounds -> bit-identical results.
template <int WPL, int CAP, bool HASBIAS, int M, int SRCROWS, bool OUTHALF>
__global__ __launch_bounds__(256)
void agg_kernel(const unsigned* __restrict__ bm, const __half* __restrict__ src,
                void* __restrict__ dstv, const float* __restrict__ bias) {
    __shared__ unsigned sidx[8][CAP];

    const int tid = threadIdx.x;
    const int lane = tid & 31;
    const int wid = tid >> 5;
    const int gw = blockIdx.x * 8 + wid;   // (b,m)
    const int b = gw / M;

    // ---- decode bitmap -> smem byte-offset list ----
    unsigned w[WPL];
    const unsigned* __restrict__ W = bm + (size_t)gw * (WPL * 32);
    if (WPL == 4) {
        const uint4 v = ((const uint4*)W)[lane];
        w[0] = v.x; w[1] = v.y; w[2] = v.z; w[3] = v.w;
    } else {
        const uint2 v = ((const uint2*)W)[lane];
        w[0] = v.x; w[1] = v.y;
    }
    int cnt = 0;
#pragma unroll
    for (int k = 0; k < WPL; k++) cnt += __popc(w[k]);

    int pre = cnt;
#pragma unroll
    for (int d = 1; d < 32; d <<= 1) {
        int v = __shfl_up_sync(0xffffffffu, pre, d);
        if (lane >= d) pre += v;
    }
    const int deg = __shfl_sync(0xffffffffu, pre, 31);
    const int deg8 = deg & ~7;
    int off = pre - cnt;

    unsigned* __restrict__ s = sidx[wid];
#pragma unroll
    for (int k = 0; k < WPL; k++) {
        const int wi = lane * WPL + k;
        unsigned bits = w[k];
        while (bits) {
            const int t = __ffs(bits) - 1;
            bits &= bits - 1;
            int slot = off;
            if (off < deg8)
                slot = (off & ~7) | ((off & 1) << 2) | ((off & 7) >> 1);
            if (slot < CAP) s[slot] = (unsigned)((wi * 32 + t) * (CC * 2));
            off++;
        }
    }
    __syncwarp();

    // ---- gather: half-warp per row; 8 rows/iter; depth-2 fp16 tree ----
    const int half = lane >> 4;
    const int hl = lane & 15;             // uint2 = cols hl*4 .. hl*4+3
    const char* __restrict__ Sb =
        (const char*)src + (size_t)b * (SRCROWS * (CC * 2)) + hl * 8;

    ull accA = 0ull, accB = 0ull;
    int i = 0;
    for (; i + 8 <= deg; i += 8) {
        const uint4 o = *(const uint4*)&s[i + half * 4];
        const uint2 u0 = *(const uint2*)(Sb + o.x);
        const uint2 u1 = *(const uint2*)(Sb + o.y);
        const uint2 u2 = *(const uint2*)(Sb + o.z);
        const uint2 u3 = *(const uint2*)(Sb + o.w);
        const __half2 pa = __hadd2(__hadd2(*(const __half2*)&u0.x, *(const __half2*)&u1.x),
                                   __hadd2(*(const __half2*)&u2.x, *(const __half2*)&u3.x));
        const __half2 pb = __hadd2(__hadd2(*(const __half2*)&u0.y, *(const __half2*)&u1.y),
                                   __hadd2(*(const __half2*)&u2.y, *(const __half2*)&u3.y));
        accA = fadd2(accA, f2ull(__half22float2(pa)));
        accB = fadd2(accB, f2ull(__half22float2(pb)));
    }
    for (; i + 4 <= deg; i += 4) {
        const uint2 u0 = *(const uint2*)(Sb + s[i + half]);
        const uint2 u1 = *(const uint2*)(Sb + s[i + 2 + half]);
        const __half2 pa = __hadd2(*(const __half2*)&u0.x, *(const __half2*)&u1.x);
        const __half2 pb = __hadd2(*(const __half2*)&u0.y, *(const __half2*)&u1.y);
        accA = fadd2(accA, f2ull(__half22float2(pa)));
        accB = fadd2(accB, f2ull(__half22float2(pb)));
    }
    if (i + 2 <= deg) {
        const uint2 u = *(const uint2*)(Sb + s[i + half]);
        accA = fadd2(accA, f2ull(__half22float2(*(const __half2*)&u.x)));
        accB = fadd2(accB, f2ull(__half22float2(*(const __half2*)&u.y)));
        i += 2;
    }
    if (i < deg && half == 0) {
        const uint2 u = *(const uint2*)(Sb + s[i]);
        accA = fadd2(accA, f2ull(__half22float2(*(const __half2*)&u.x)));
        accB = fadd2(accB, f2ull(__half22float2(*(const __half2*)&u.y)));
    }

    // combine halves
    float v0 = ((const float2*)&accA)->x;
    float v1 = ((const float2*)&accA)->y;
    float v2 = ((const float2*)&accB)->x;
    float v3 = ((const float2*)&accB)->y;
    v0 += __shfl_xor_sync(0xffffffffu, v0, 16);
    v1 += __shfl_xor_sync(0xffffffffu, v1, 16);
    v2 += __shfl_xor_sync(0xffffffffu, v2, 16);
    v3 += __shfl_xor_sync(0xffffffffu, v3, 16);

    const float inv = 1.0f / (float)deg;   // degrees guaranteed > 0
    v0 *= inv; v1 *= inv; v2 *= inv; v3 *= inv;
    if (HASBIAS) {
        const float4 bv = ((const float4*)bias)[hl];
        v0 += bv.x; v1 += bv.y; v2 += bv.z; v3 += bv.w;
    }
    if (half == 0) {
        if (OUTHALF) {
            __half2 h0 = __float22half2_rn(make_float2(v0, v1));
            __half2 h1 = __float22half2_rn(make_float2(v2, v3));
            uint2 o;
            o.x = *(unsigned*)&h0;
            o.y = *(unsigned*)&h1;
            ((uint2*)((__half*)dstv + (size_t)gw * CC))[hl] = o;
        } else {
            ((float4*)((float*)dstv + (size_t)gw * CC))[hl] =
                make_float4(v0, v1, v2, v3);
        }
    }
}

// ---------------- launch ----------------
extern "C" void kernel_launch(void* const* d_in, const int* in_sizes, int n_in,
                              void* d_out, int out_size) {
    const float* x = (const float*)d_in[0];
    const float* H = (const float*)d_in[1];
    const float* theta = (const float*)d_in[2];
    const float* bias = (const float*)d_in[3];
    float* out = (float*)d_out;

    __half *xt, *he;
    unsigned *ebm, *nbm;
    cudaGetSymbolAddress((void**)&xt, g_xt);
    cudaGetSymbolAddress((void**)&he, g_he);
    cudaGetSymbolAddress((void**)&ebm, g_ebm);
    cudaGetSymbolAddress((void**)&nbm, g_nbm);

    // 0: zero ebm (required before build's atomics)
    zero_kernel<<<1024, 256>>>();
    // 1: fused xt (CTAs 0..2047) + build (CTAs 2048..6143)
    buildxt_kernel<<<(BB * NN) / 8 + (BB * NN) / 4, 256>>>(H, x, theta);
    // 2: he = mean_{n in e} xt[n]  (fp16 out)
    agg_kernel<4, ECAP, false, EE, NN, true>
        <<<(BB * EE) / 8, 256>>>(ebm, xt, he, nullptr);
    // 3: out = mean_{e in n} he[e] + bias  (fp32 out)
    agg_kernel<2, NCAP, true, NN, EE, false>
        <<<(BB * NN) / 8, 256>>>(nbm, he, out, bias);
}